// round 4
// baseline (speedup 1.0000x reference)
#include <cuda_runtime.h>
#include <math.h>
#include <stdint.h>

#define B   8
#define H   16
#define HD  128
#define D   2048
#define NB  512
#define BS  64
#define MB  64
#define KV  (MB*BS)      // 4096
#define NCHUNK 8
#define CHUNK  (KV/NCHUNK)  // 512

// ---------------- scratch (no allocations allowed) ----------------
__device__ float g_q[B*D];
__device__ float g_k[B*D];
__device__ float g_v[B*D];
__device__ float g_o[B*D];
__device__ float g_pm[B*H*NCHUNK];
__device__ float g_pl[B*H*NCHUNK];
__device__ float g_po[B*H*NCHUNK*HD];

__device__ __forceinline__ float warp_sum(float v) {
#pragma unroll
    for (int o = 16; o; o >>= 1) v += __shfl_xor_sync(0xffffffffu, v, o);
    return v;
}

// ---------------- tiled GEMV: 16 columns per block, X staged in smem ----------
template<int WHICH_SEL>
__device__ __forceinline__ void gemv16_body(
    const float* __restrict__ X, const float* __restrict__ W,
    const float* __restrict__ bias, float* __restrict__ out, int cblk)
{
    int tid = threadIdx.x, lane = tid & 31, w = tid >> 5;
    int c0 = cblk * 16 + w * 4;

    __shared__ float sX[B][1024];
    float acc[4][B];
#pragma unroll
    for (int j = 0; j < 4; j++)
#pragma unroll
        for (int b = 0; b < B; b++) acc[j][b] = 0.f;

#pragma unroll
    for (int p = 0; p < 2; p++) {
        __syncthreads();
        for (int i = tid; i < B * 256; i += 128) {
            int b = i >> 8, j = i & 255;
            ((float4*)sX[b])[j] = ((const float4*)(X + (size_t)b * D + p * 1024))[j];
        }
        __syncthreads();
#pragma unroll
        for (int kk = 0; kk < 1024; kk += 128) {
            int k = kk + lane * 4;
            float4 w4[4];
#pragma unroll
            for (int j = 0; j < 4; j++)
                w4[j] = *(const float4*)(W + (size_t)(c0 + j) * D + p * 1024 + k);
#pragma unroll
            for (int b = 0; b < B; b++) {
                float4 x4 = *(const float4*)(&sX[b][k]);
#pragma unroll
                for (int j = 0; j < 4; j++)
                    acc[j][b] += w4[j].x*x4.x + w4[j].y*x4.y + w4[j].z*x4.z + w4[j].w*x4.w;
            }
        }
    }

#pragma unroll
    for (int j = 0; j < 4; j++)
#pragma unroll
        for (int b = 0; b < B; b++) {
            float s = warp_sum(acc[j][b]);
            if (lane == j * 8 + b)
                out[(size_t)b * D + c0 + j] = s + bias[c0 + j];
        }
}

__global__ void __launch_bounds__(128) qkv_kernel(
    const float* __restrict__ X,
    const float* __restrict__ Wq, const float* __restrict__ bq,
    const float* __restrict__ Wk, const float* __restrict__ bk,
    const float* __restrict__ Wv, const float* __restrict__ bv)
{
    int which = blockIdx.x >> 7;
    int cblk  = blockIdx.x & 127;
    const float* W    = (which == 0) ? Wq : (which == 1) ? Wk : Wv;
    const float* bias = (which == 0) ? bq : (which == 1) ? bk : bv;
    float* out        = (which == 0) ? g_q : (which == 1) ? g_k : g_v;
    gemv16_body<0>(X, W, bias, out, cblk);
}

__global__ void __launch_bounds__(128) oproj_kernel(
    const float* __restrict__ W, const float* __restrict__ bias,
    float* __restrict__ out)
{
    gemv16_body<1>(g_o, W, bias, out, blockIdx.x);
}

// ---------------- RoPE on q and k (fp32 fast path) ----------------
__global__ void rope_qk(const int* __restrict__ hist) {
    int bh = blockIdx.x;        // b*H + h
    int b  = bh >> 4;
    int d  = threadIdx.x;       // 0..63
    int pos = hist[b];
    float inv = exp2f((float)d * -0.2076205059304601f);
    float f   = (float)pos * inv;
    float sf, cf;
    sincosf(f, &sf, &cf);
    int base = bh * HD;
    {
        float x1 = g_q[base + d], x2 = g_q[base + d + 64];
        g_q[base + d]      = x1*cf - x2*sf;
        g_q[base + d + 64] = x2*cf + x1*sf;
    }
    {
        float x1 = g_k[base + d], x2 = g_k[base + d + 64];
        g_k[base + d]      = x1*cf - x2*sf;
        g_k[base + d + 64] = x2*cf + x1*sf;
    }
}

// ---------------- split-KV attention partial ----------------
// 128 threads = 4 warps. Each warp: 8 keys/iteration, one key per 8-lane
// group x 2 quads. Dot product reduced with 3-level width-8 butterfly; the
// group-replicated scores need only xor-8/xor-16 for the warp max. Offsets
// (shared by K and V) computed once per key, SHFL-broadcast to the V phase.
// NOTE: pA/pB (and therefore the running l) are GROUP-LOCAL; the running l
// must be butterfly-summed across groups (xor 8, 16) before the warp merge.
__global__ void __launch_bounds__(128) attn_partial(
    const float* __restrict__ kc, const float* __restrict__ vc,
    const int* __restrict__ hist, const int* __restrict__ bofs)
{
    int c = blockIdx.x, h = blockIdx.y, b = blockIdx.z;
    int pos = hist[b];
    int L = pos + 1;
    int s0 = c * CHUNK;
    int idx = (b*H + h)*NCHUNK + c;
    int tid = threadIdx.x, lane = tid & 31, w = tid >> 5;

    if (s0 >= L) {
        if (tid == 0) { g_pm[idx] = -1e30f; g_pl[idx] = 0.f; }
        return;
    }
    int s1 = min(s0 + CHUNK, L);

    __shared__ int sblk[MB];
    if (tid < MB) sblk[tid] = bofs[b*MB + tid];
    __syncthreads();

    int g = lane >> 3;          // group 0..3 (one key per group per quad)
    int e = lane & 7;           // element within group

    const float* qp   = g_q + (size_t)b*D + h*HD;
    const float* knew = g_k + (size_t)b*D + h*HD;
    const float* vnew = g_v + (size_t)b*D + h*HD;

    float4 qf[4];
#pragma unroll
    for (int p = 0; p < 4; p++)
        qf[p] = *(const float4*)(qp + p*32 + e*4);

    const float scale = 0.08838834764831845f;  // 1/sqrt(128)
    float m = -1e30f, lacc = 0.f;
    float4 oa = make_float4(0.f, 0.f, 0.f, 0.f);

    for (int base = s0 + w*8; base < s1; base += 32) {
        int sA = base + g;
        int sB = base + 4 + g;
        int sAe = min(sA, pos);
        int sBe = min(sB, pos);

        uint32_t offA, offB;
        if (sAe == pos) offA = 0x80000000u;
        else offA = (uint32_t)(((sblk[sAe >> 6]*BS + (sAe & 63))*H + h)*HD);
        if (sBe == pos) offB = 0x80000000u;
        else offB = (uint32_t)(((sblk[sBe >> 6]*BS + (sBe & 63))*H + h)*HD);

        const float* krA = (offA & 0x80000000u) ? knew : kc + offA;
        const float* krB = (offB & 0x80000000u) ? knew : kc + offB;

        float4 ka[4], kb[4];
#pragma unroll
        for (int p = 0; p < 4; p++) {
            ka[p] = *(const float4*)(krA + p*32 + e*4);
            kb[p] = *(const float4*)(krB + p*32 + e*4);
        }

        float dA = 0.f, dB = 0.f;
#pragma unroll
        for (int p = 0; p < 4; p++) {
            dA += qf[p].x*ka[p].x + qf[p].y*ka[p].y + qf[p].z*ka[p].z + qf[p].w*ka[p].w;
            dB += qf[p].x*kb[p].x + qf[p].y*kb[p].y + qf[p].z*kb[p].z + qf[p].w*kb[p].w;
        }
        // width-8 butterfly: all 8 lanes of a group end with the full dot
#pragma unroll
        for (int o = 4; o; o >>= 1) {
            dA += __shfl_xor_sync(0xffffffffu, dA, o);
            dB += __shfl_xor_sync(0xffffffffu, dB, o);
        }
        dA = (sA < s1) ? dA * scale : -1e30f;
        dB = (sB < s1) ? dB * scale : -1e30f;

        // warp max: scores replicated within groups -> only xor 8, 16 needed
        float mx = fmaxf(dA, dB);
        mx = fmaxf(mx, __shfl_xor_sync(0xffffffffu, mx, 8));
        mx = fmaxf(mx, __shfl_xor_sync(0xffffffffu, mx, 16));

        float mn = fmaxf(m, mx);
        float corr = __expf(m - mn);
        lacc *= corr;
        oa.x *= corr; oa.y *= corr; oa.z *= corr; oa.w *= corr;
        m = mn;

        float pA = __expf(dA - mn);
        float pB = __expf(dB - mn);
        lacc += pA + pB;          // group-local; cross-group sum after the loop

        // V phase: each lane owns dims [lane*4, lane*4+4)
#pragma unroll
        for (int j = 0; j < 8; j++) {
            uint32_t off = __shfl_sync(0xffffffffu, (j < 4) ? offA : offB, (j & 3) * 8);
            float    pj  = __shfl_sync(0xffffffffu, (j < 4) ? pA   : pB,   (j & 3) * 8);
            const float* vr = (off & 0x80000000u) ? vnew : vc + off;
            float4 v4 = *(const float4*)(vr + lane*4);
            oa.x += pj * v4.x;
            oa.y += pj * v4.y;
            oa.z += pj * v4.z;
            oa.w += pj * v4.w;
        }
    }
    // lacc is group-local (all 8 lanes of a group identical). Sum the 4
    // distinct group values: xor-8 and xor-16 visit each other group once.
    lacc += __shfl_xor_sync(0xffffffffu, lacc, 8);
    lacc += __shfl_xor_sync(0xffffffffu, lacc, 16);

    // merge the 4 warps
    __shared__ float sm_m[4], sm_l[4];
    __shared__ float sm_o[4][HD];
    if (lane == 0) { sm_m[w] = m; sm_l[w] = lacc; }
    *(float4*)&sm_o[w][lane*4] = oa;
    __syncthreads();

    float M = fmaxf(fmaxf(sm_m[0], sm_m[1]), fmaxf(sm_m[2], sm_m[3]));
    float f0 = (sm_l[0] > 0.f) ? __expf(sm_m[0] - M) : 0.f;
    float f1 = (sm_l[1] > 0.f) ? __expf(sm_m[1] - M) : 0.f;
    float f2 = (sm_l[2] > 0.f) ? __expf(sm_m[2] - M) : 0.f;
    float f3 = (sm_l[3] > 0.f) ? __expf(sm_m[3] - M) : 0.f;

    int d = tid;  // 0..127
    float acc = sm_o[0][d]*f0 + sm_o[1][d]*f1 + sm_o[2][d]*f2 + sm_o[3][d]*f3;
    g_po[(size_t)idx*HD + d] = acc;
    if (tid == 0) {
        g_pm[idx] = M;
        g_pl[idx] = sm_l[0]*f0 + sm_l[1]*f1 + sm_l[2]*f2 + sm_l[3]*f3;
    }
}

// ---------------- combine split-KV partials (float4 per thread) ----------------
__global__ void __launch_bounds__(32) attn_combine() {
    int bh = blockIdx.x;    // b*H + h
    int t  = threadIdx.x;   // 0..31, dims t*4..t*4+3
    float M = -1e30f;
#pragma unroll
    for (int c = 0; c < NCHUNK; c++) M = fmaxf(M, g_pm[bh*NCHUNK + c]);
    float Ls = 0.f;
    float4 acc = make_float4(0.f, 0.f, 0.f, 0.f);
#pragma unroll
    for (int c = 0; c < NCHUNK; c++) {
        float lc = g_pl[bh*NCHUNK + c];
        float f = (lc > 0.f) ? __expf(g_pm[bh*NCHUNK + c] - M) : 0.f;
        Ls += lc * f;
        float4 p4 = *(const float4*)(g_po + (size_t)(bh*NCHUNK + c)*HD + t*4);
        acc.x += p4.x * f;
        acc.y += p4.y * f;
        acc.z += p4.z * f;
        acc.w += p4.w * f;
    }
    float inv = 1.f / Ls;
    float4 r = make_float4(acc.x*inv, acc.y*inv, acc.z*inv, acc.w*inv);
    *(float4*)(g_o + (size_t)bh*HD + t*4) = r;
}

// ---------------- entry point ----------------
extern "C" void kernel_launch(void* const* d_in, const int* in_sizes, int n_in,
                              void* d_out, int out_size) {
    const float* hs   = (const float*)d_in[0];
    const float* kc   = (const float*)d_in[1];
    const float* vc   = (const float*)d_in[2];
    const float* Wq   = (const float*)d_in[3];
    const float* bq   = (const float*)d_in[4];
    const float* Wk   = (const float*)d_in[5];
    const float* bk   = (const float*)d_in[6];
    const float* Wv   = (const float*)d_in[7];
    const float* bv   = (const float*)d_in[8];
    const float* Wo   = (const float*)d_in[9];
    const float* bo   = (const float*)d_in[10];
    const int*   hist = (const int*)d_in[11];
    const int*   bofs = (const int*)d_in[12];
    float* out = (float*)d_out;

    qkv_kernel<<<3*128, 128>>>(hs, Wq, bq, Wk, bk, Wv, bv);
    rope_qk<<<B*H, 64>>>(hist);
    attn_partial<<<dim3(NCHUNK, H, B), 128>>>(kc, vc, hist, bofs);
    attn_combine<<<B*H, 32>>>();
    oproj_kernel<<<128, 128>>>(Wo, bo, out);
}

// round 5
// speedup vs baseline: 1.1935x; 1.1935x over previous
#include <cuda_runtime.h>
#include <math.h>
#include <stdint.h>

#define B   8
#define H   16
#define HD  128
#define D   2048
#define NB  512
#define BS  64
#define MB  64
#define KV  (MB*BS)        // 4096
#define NCHUNK 16
#define CHUNK  (KV/NCHUNK) // 256

// ---------------- scratch (no allocations allowed) ----------------
__device__ float g_q[B*D];
__device__ float g_k[B*D];
__device__ float g_v[B*D];
__device__ float g_o[B*D];
__device__ float g_pm[B*H*NCHUNK];
__device__ float g_pl[B*H*NCHUNK];
__device__ float g_po[B*H*NCHUNK*HD];

__device__ __forceinline__ float warp_sum(float v) {
#pragma unroll
    for (int o = 16; o; o >>= 1) v += __shfl_xor_sync(0xffffffffu, v, o);
    return v;
}

// ---------------- tiled GEMV: 16 columns per block, X staged in smem ----------
template<int WHICH_SEL>
__device__ __forceinline__ void gemv16_body(
    const float* __restrict__ X, const float* __restrict__ W,
    const float* __restrict__ bias, float* __restrict__ out, int cblk)
{
    int tid = threadIdx.x, lane = tid & 31, w = tid >> 5;
    int c0 = cblk * 16 + w * 4;

    __shared__ float sX[B][1024];
    float acc[4][B];
#pragma unroll
    for (int j = 0; j < 4; j++)
#pragma unroll
        for (int b = 0; b < B; b++) acc[j][b] = 0.f;

#pragma unroll
    for (int p = 0; p < 2; p++) {
        __syncthreads();
        for (int i = tid; i < B * 256; i += 128) {
            int b = i >> 8, j = i & 255;
            ((float4*)sX[b])[j] = ((const float4*)(X + (size_t)b * D + p * 1024))[j];
        }
        __syncthreads();
#pragma unroll
        for (int kk = 0; kk < 1024; kk += 128) {
            int k = kk + lane * 4;
            float4 w4[4];
#pragma unroll
            for (int j = 0; j < 4; j++)
                w4[j] = *(const float4*)(W + (size_t)(c0 + j) * D + p * 1024 + k);
#pragma unroll
            for (int b = 0; b < B; b++) {
                float4 x4 = *(const float4*)(&sX[b][k]);
#pragma unroll
                for (int j = 0; j < 4; j++)
                    acc[j][b] += w4[j].x*x4.x + w4[j].y*x4.y + w4[j].z*x4.z + w4[j].w*x4.w;
            }
        }
    }

#pragma unroll
    for (int j = 0; j < 4; j++)
#pragma unroll
        for (int b = 0; b < B; b++) {
            float s = warp_sum(acc[j][b]);
            if (lane == j * 8 + b)
                out[(size_t)b * D + c0 + j] = s + bias[c0 + j];
        }
}

__global__ void __launch_bounds__(128) qkv_kernel(
    const float* __restrict__ X,
    const float* __restrict__ Wq, const float* __restrict__ bq,
    const float* __restrict__ Wk, const float* __restrict__ bk,
    const float* __restrict__ Wv, const float* __restrict__ bv)
{
    int which = blockIdx.x >> 7;
    int cblk  = blockIdx.x & 127;
    const float* W    = (which == 0) ? Wq : (which == 1) ? Wk : Wv;
    const float* bias = (which == 0) ? bq : (which == 1) ? bk : bv;
    float* out        = (which == 0) ? g_q : (which == 1) ? g_k : g_v;
    gemv16_body<0>(X, W, bias, out, cblk);
}

__global__ void __launch_bounds__(128) oproj_kernel(
    const float* __restrict__ W, const float* __restrict__ bias,
    float* __restrict__ out)
{
    gemv16_body<1>(g_o, W, bias, out, blockIdx.x);
}

// ---------------- RoPE on q and k (fp32 fast path) ----------------
__global__ void rope_qk(const int* __restrict__ hist) {
    int bh = blockIdx.x;
    int b  = bh >> 4;
    int d  = threadIdx.x;       // 0..63
    int pos = hist[b];
    float inv = exp2f((float)d * -0.2076205059304601f);
    float f   = (float)pos * inv;
    float sf, cf;
    sincosf(f, &sf, &cf);
    int base = bh * HD;
    {
        float x1 = g_q[base + d], x2 = g_q[base + d + 64];
        g_q[base + d]      = x1*cf - x2*sf;
        g_q[base + d + 64] = x2*cf + x1*sf;
    }
    {
        float x1 = g_k[base + d], x2 = g_k[base + d + 64];
        g_k[base + d]      = x1*cf - x2*sf;
        g_k[base + d + 64] = x2*cf + x1*sf;
    }
}

// ---------------- split-KV attention partial (R2 structure, pipelined) -------
// 128 threads = 4 warps; warp processes 4 keys/iteration (warp-wide float4
// rows). Addresses clamped to min(s,pos) so every load is unconditionally
// valid; out-of-range keys get score -1e30 -> p = 0. The next iteration's 8
// K/V loads are issued BEFORE the current iteration's softmax math, keeping
// ~16 LDG.128 in flight per warp (DRAM latency hidden behind compute).
__global__ void __launch_bounds__(128) attn_partial(
    const float* __restrict__ kc, const float* __restrict__ vc,
    const int* __restrict__ hist, const int* __restrict__ bofs)
{
    int c = blockIdx.x, h = blockIdx.y, b = blockIdx.z;
    int pos = hist[b];
    int L = pos + 1;
    int s0 = c * CHUNK;
    int idx = (b*H + h)*NCHUNK + c;
    int tid = threadIdx.x, lane = tid & 31, w = tid >> 5;

    if (s0 >= L) {
        if (tid == 0) { g_pm[idx] = -1e30f; g_pl[idx] = 0.f; }
        return;
    }
    int s1 = min(s0 + CHUNK, L);

    __shared__ int sblk[MB];
    if (tid < MB) sblk[tid] = bofs[b*MB + tid];
    __syncthreads();

    const float* qp   = g_q + (size_t)b*D + h*HD;
    const float* knew = g_k + (size_t)b*D + h*HD;
    const float* vnew = g_v + (size_t)b*D + h*HD;

    float4 q4 = *(const float4*)(qp + lane*4);
    const float scale = 0.08838834764831845f;  // 1/sqrt(128)

    float m = -1e30f, lacc = 0.f;
    float4 oa = make_float4(0.f, 0.f, 0.f, 0.f);

    int base = s0 + w*4;

    // address+load helper (clamped, always safe)
    float4 k4[4], v4[4];
#pragma unroll
    for (int i = 0; i < 4; i++) {
        int s = min(base + i, pos);
        const float *kr, *vr;
        if (s == pos) { kr = knew; vr = vnew; }
        else {
            size_t off = (((size_t)sblk[s >> 6]*BS + (s & 63))*H + h)*(size_t)HD;
            kr = kc + off; vr = vc + off;
        }
        k4[i] = *(const float4*)(kr + lane*4);
        v4[i] = *(const float4*)(vr + lane*4);
    }

    for (; base < s1; base += 16) {
        // ---- issue next iteration's loads first ----
        int nbase = base + 16;
        int pbase = (nbase < s1) ? nbase : base;   // harmless re-load on last iter
        float4 kn[4], vn[4];
#pragma unroll
        for (int i = 0; i < 4; i++) {
            int s = min(pbase + i, pos);
            const float *kr, *vr;
            if (s == pos) { kr = knew; vr = vnew; }
            else {
                size_t off = (((size_t)sblk[s >> 6]*BS + (s & 63))*H + h)*(size_t)HD;
                kr = kc + off; vr = vc + off;
            }
            kn[i] = *(const float4*)(kr + lane*4);
            vn[i] = *(const float4*)(vr + lane*4);
        }

        // ---- process current 4 keys ----
        float sc[4];
#pragma unroll
        for (int i = 0; i < 4; i++) {
            float dv = q4.x*k4[i].x + q4.y*k4[i].y + q4.z*k4[i].z + q4.w*k4[i].w;
            sc[i] = warp_sum(dv) * scale;
            if (base + i >= s1) sc[i] = -1e30f;
        }
        float mx = fmaxf(fmaxf(sc[0], sc[1]), fmaxf(sc[2], sc[3]));
        float mn = fmaxf(m, mx);
        float corr = __expf(m - mn);
        lacc *= corr;
        oa.x *= corr; oa.y *= corr; oa.z *= corr; oa.w *= corr;
#pragma unroll
        for (int i = 0; i < 4; i++) {
            float p = __expf(sc[i] - mn);
            lacc += p;
            oa.x += p * v4[i].x;
            oa.y += p * v4[i].y;
            oa.z += p * v4[i].z;
            oa.w += p * v4[i].w;
        }
        m = mn;

        // ---- rotate ----
#pragma unroll
        for (int i = 0; i < 4; i++) { k4[i] = kn[i]; v4[i] = vn[i]; }
    }

    // merge the 4 warps
    __shared__ float sm_m[4], sm_l[4];
    __shared__ float sm_o[4][HD];
    if (lane == 0) { sm_m[w] = m; sm_l[w] = lacc; }
    *(float4*)&sm_o[w][lane*4] = oa;
    __syncthreads();

    float M = fmaxf(fmaxf(sm_m[0], sm_m[1]), fmaxf(sm_m[2], sm_m[3]));
    float f0 = (sm_l[0] > 0.f) ? __expf(sm_m[0] - M) : 0.f;
    float f1 = (sm_l[1] > 0.f) ? __expf(sm_m[1] - M) : 0.f;
    float f2 = (sm_l[2] > 0.f) ? __expf(sm_m[2] - M) : 0.f;
    float f3 = (sm_l[3] > 0.f) ? __expf(sm_m[3] - M) : 0.f;

    int d = tid;
    float acc = sm_o[0][d]*f0 + sm_o[1][d]*f1 + sm_o[2][d]*f2 + sm_o[3][d]*f3;
    g_po[(size_t)idx*HD + d] = acc;
    if (tid == 0) {
        g_pm[idx] = M;
        g_pl[idx] = sm_l[0]*f0 + sm_l[1]*f1 + sm_l[2]*f2 + sm_l[3]*f3;
    }
}

// ---------------- combine split-KV partials (float4 per thread) ----------------
__global__ void __launch_bounds__(32) attn_combine() {
    int bh = blockIdx.x;
    int t  = threadIdx.x;
    float M = -1e30f;
#pragma unroll
    for (int c = 0; c < NCHUNK; c++) M = fmaxf(M, g_pm[bh*NCHUNK + c]);
    float Ls = 0.f;
    float4 acc = make_float4(0.f, 0.f, 0.f, 0.f);
#pragma unroll
    for (int c = 0; c < NCHUNK; c++) {
        float lc = g_pl[bh*NCHUNK + c];
        float f = (lc > 0.f) ? __expf(g_pm[bh*NCHUNK + c] - M) : 0.f;
        Ls += lc * f;
        float4 p4 = *(const float4*)(g_po + (size_t)(bh*NCHUNK + c)*HD + t*4);
        acc.x += p4.x * f;
        acc.y += p4.y * f;
        acc.z += p4.z * f;
        acc.w += p4.w * f;
    }
    float inv = 1.f / Ls;
    float4 r = make_float4(acc.x*inv, acc.y*inv, acc.z*inv, acc.w*inv);
    *(float4*)(g_o + (size_t)bh*HD + t*4) = r;
}

// ---------------- entry point ----------------
extern "C" void kernel_launch(void* const* d_in, const int* in_sizes, int n_in,
                              void* d_out, int out_size) {
    const float* hs   = (const float*)d_in[0];
    const float* kc   = (const float*)d_in[1];
    const float* vc   = (const float*)d_in[2];
    const float* Wq   = (const float*)d_in[3];
    const float* bq   = (const float*)d_in[4];
    const float* Wk   = (const float*)d_in[5];
    const float* bk   = (const float*)d_in[6];
    const float* Wv   = (const float*)d_in[7];
    const float* bv   = (const float*)d_in[8];
    const float* Wo   = (const float*)d_in[9];
    const float* bo   = (const float*)d_in[10];
    const int*   hist = (const int*)d_in[11];
    const int*   bofs = (const int*)d_in[12];
    float* out = (float*)d_out;

    qkv_kernel<<<3*128, 128>>>(hs, Wq, bq, Wk, bk, Wv, bv);
    rope_qk<<<B*H, 64>>>(hist);
    attn_partial<<<dim3(NCHUNK, H, B), 128>>>(kc, vc, hist, bofs);
    attn_combine<<<B*H, 32>>>();
    oproj_kernel<<<128, 128>>>(Wo, bo, out);
}